// round 11
// baseline (speedup 1.0000x reference)
#include <cuda_runtime.h>
#include <cuda_bf16.h>
#include <math.h>

#define BATCH 16384
#define DIM   1024
#define NLAYERS 6

#define BM 128
#define BN 128
#define BK 32
#define STAGES 3
// swizzled layout: 64B rows (32 bf16), chunk' = chunk ^ ((row>>1)&3)
#define ARR_BYTES (BM * 64)                      // 8192 per operand array
#define STAGE_BYTES (4 * ARR_BYTES)              // 32768
#define SMEM_TOTAL_BYTES (STAGES * STAGE_BYTES)  // 98304 -> 2 CTAs/SM

// ---- scratch (allocation-free: __device__ globals; device-code refs only) ----
__device__ float g_h[(size_t)BATCH * DIM];
__device__ __nv_bfloat16 g_hh[(size_t)BATCH * DIM];
__device__ __nv_bfloat16 g_hl[(size_t)BATCH * DIM];
__device__ __nv_bfloat16 g_th[(size_t)BATCH * DIM];
__device__ __nv_bfloat16 g_tl[(size_t)BATCH * DIM];
__device__ __nv_bfloat16 g_W1h[DIM * DIM], g_W1l[DIM * DIM];
__device__ __nv_bfloat16 g_W2h[DIM * DIM], g_W2l[DIM * DIM];
__device__ float g_dirs[3 * DIM];
__device__ float g_dn2[3];
__device__ float g_coef[(size_t)BATCH * 3];

static __device__ __forceinline__ float dot4(const float4 a, const float4 b) {
    return a.x * b.x + a.y * b.y + a.z * b.z + a.w * b.w;
}

static __device__ __forceinline__ void split2(float x, __nv_bfloat16& h, __nv_bfloat16& l) {
    h = __float2bfloat16(x);
    l = __float2bfloat16(x - __bfloat162float(h));
}

static __device__ __forceinline__ void mma16816(float* c, const unsigned* a, const unsigned* b) {
    asm volatile(
        "mma.sync.aligned.m16n8k16.row.col.f32.bf16.bf16.f32 "
        "{%0,%1,%2,%3}, {%4,%5,%6,%7}, {%8,%9}, {%0,%1,%2,%3};\n"
        : "+f"(c[0]), "+f"(c[1]), "+f"(c[2]), "+f"(c[3])
        : "r"(a[0]), "r"(a[1]), "r"(a[2]), "r"(a[3]), "r"(b[0]), "r"(b[1]));
}

#define LDSM_X4(r, a) \
    asm volatile("ldmatrix.sync.aligned.m8n8.x4.shared.b16 {%0,%1,%2,%3}, [%4];" \
        : "=r"((r)[0]), "=r"((r)[1]), "=r"((r)[2]), "=r"((r)[3]) : "r"(a))

static __device__ __forceinline__ unsigned smem_u32(const void* p) {
    return (unsigned)__cvta_generic_to_shared(p);
}

// swizzled byte offset of 16B chunk (row, chunk) within an operand array
static __device__ __forceinline__ unsigned swoff(int row, int chunk) {
    return (unsigned)(row * 64 + ((chunk ^ ((row >> 1) & 3)) << 4));
}

static __device__ __forceinline__ void cp16(unsigned dst, const void* src) {
    asm volatile("cp.async.cg.shared.global [%0], [%1], 16;\n" :: "r"(dst), "l"(src));
}
static __device__ __forceinline__ void cp_commit() {
    asm volatile("cp.async.commit_group;\n");
}
template <int N>
static __device__ __forceinline__ void cp_wait() {
    asm volatile("cp.async.wait_group %0;\n" :: "n"(N));
}

// ---------------------------------------------------------------------------
__global__ void wsplit_kernel(const float* __restrict__ W1, const float* __restrict__ W2) {
    const size_t i = (size_t)blockIdx.x * 256 + threadIdx.x;
    float x = W1[i];
    split2(x, g_W1h[i], g_W1l[i]);
    x = W2[i];
    split2(x, g_W2h[i], g_W2l[i]);
}

__global__ void anchor_kernel(const float* __restrict__ ae,
                              const float* __restrict__ ac,
                              const float* __restrict__ an) {
    const int b = blockIdx.x;
    const int t = threadIdx.x;
    const float* src = (b == 0) ? ae : ((b == 1) ? ac : an);
    float4 v = reinterpret_cast<const float4*>(src)[t];
    float s = dot4(v, v);
#pragma unroll
    for (int o = 16; o; o >>= 1) s += __shfl_down_sync(0xffffffffu, s, o);
    __shared__ float sh[8];
    if ((t & 31) == 0) sh[t >> 5] = s;
    __syncthreads();
    __shared__ float s_inv;
    if (t == 0) {
        float tot = 0.f;
#pragma unroll
        for (int i = 0; i < 8; ++i) tot += sh[i];
        s_inv = 1.0f / fmaxf(sqrtf(tot), 1e-12f);
    }
    __syncthreads();
    const float inv = s_inv;
    v.x *= inv; v.y *= inv; v.z *= inv; v.w *= inv;
    reinterpret_cast<float4*>(g_dirs + (size_t)b * DIM)[t] = v;

    float s2 = dot4(v, v);
#pragma unroll
    for (int o = 16; o; o >>= 1) s2 += __shfl_down_sync(0xffffffffu, s2, o);
    __syncthreads();
    if ((t & 31) == 0) sh[t >> 5] = s2;
    __syncthreads();
    if (t == 0) {
        float tot = 0.f;
#pragma unroll
        for (int i = 0; i < 8; ++i) tot += sh[i];
        g_dn2[b] = tot;
    }
}

// ---------------------------------------------------------------------------
// Warp-per-row prep (shfl_xor only). 8 rows per 256-block.
// ---------------------------------------------------------------------------
__global__ void prep_kernel(const float* __restrict__ Hext, int use_ext, int do_clamp) {
    const int row  = (blockIdx.x * 256 + threadIdx.x) >> 5;
    const int lane = threadIdx.x & 31;
    const float* hrow = use_ext ? (Hext + (size_t)row * DIM) : (g_h + (size_t)row * DIM);

    float4 hv[8];
    float s2 = 0.f, de = 0.f, dc = 0.f, dn = 0.f;
#pragma unroll
    for (int j = 0; j < 8; ++j) {
        const int idx = lane + j * 32;
        hv[j] = reinterpret_cast<const float4*>(hrow)[idx];
        const float4 ev = reinterpret_cast<const float4*>(g_dirs)[idx];
        const float4 cv = reinterpret_cast<const float4*>(g_dirs + DIM)[idx];
        const float4 nv = reinterpret_cast<const float4*>(g_dirs + 2 * DIM)[idx];
        s2 += dot4(hv[j], hv[j]);
        de += dot4(hv[j], ev);
        dc += dot4(hv[j], cv);
        dn += dot4(hv[j], nv);
    }
#pragma unroll
    for (int o = 16; o; o >>= 1) {
        s2 += __shfl_xor_sync(0xffffffffu, s2, o);
        de += __shfl_xor_sync(0xffffffffu, de, o);
        dc += __shfl_xor_sync(0xffffffffu, dc, o);
        dn += __shfl_xor_sync(0xffffffffu, dn, o);
    }

    float scale = 1.0f;
    if (do_clamp) {
        const float nrm = sqrtf(s2);
        if (nrm > 10.0f) scale = 10.0f / (nrm + 1e-8f);
    }
    const float S2 = s2 * scale * scale;
    const float DE = de * scale, DC = dc * scale, DN = dn * scale;

    if (lane == 0) {
        const float hn = fmaxf(sqrtf(S2), 1e-12f);
        const float a_e = DE / hn, a_c = DC / hn, a_n = DN / hn;
        const float div_e = 1.0f - a_e, div_c = 1.0f - a_c, div_n = 1.0f - a_n;
        const float boundary = fminf(fmaxf(1.0f - fabsf(a_e - a_c), 0.0f), 1.0f);
        const float fe = fmaxf(sqrtf(fmaxf(S2 - 2.0f * DE + g_dn2[0], 0.0f)), 1e-12f);
        const float fc = fmaxf(sqrtf(fmaxf(S2 - 2.0f * DC + g_dn2[1], 0.0f)), 1e-12f);
        const float fn = fmaxf(sqrtf(fmaxf(S2 - 2.0f * DN + g_dn2[2], 0.0f)), 1e-12f);
        g_coef[(size_t)row * 3 + 0] = 0.1f  * div_e / fe;
        g_coef[(size_t)row * 3 + 1] = 0.1f  * div_c / fc;
        g_coef[(size_t)row * 3 + 2] = (0.05f * div_n + 0.05f * boundary) / fn;
    }

    const bool store_h = (use_ext != 0) || (scale != 1.0f);
#pragma unroll
    for (int j = 0; j < 8; ++j) {
        const int idx = lane + j * 32;
        float4 v = hv[j];
        v.x *= scale; v.y *= scale; v.z *= scale; v.w *= scale;
        if (store_h) reinterpret_cast<float4*>(g_h + (size_t)row * DIM)[idx] = v;
        __nv_bfloat16 hh[4], hl[4];
        split2(v.x, hh[0], hl[0]);
        split2(v.y, hh[1], hl[1]);
        split2(v.z, hh[2], hl[2]);
        split2(v.w, hh[3], hl[3]);
        reinterpret_cast<uint2*>(g_hh + (size_t)row * DIM)[idx] = *reinterpret_cast<uint2*>(hh);
        reinterpret_cast<uint2*>(g_hl + (size_t)row * DIM)[idx] = *reinterpret_cast<uint2*>(hl);
    }
}

// ---------------------------------------------------------------------------
// Tensor-core NT GEMM, bf16x3, 128x128x32 tiles, XOR-swizzled smem,
// 3-stage cp.async ring, ONE barrier per K-step, 2 CTAs/SM.
// 128 threads = 4 warps (2x2), warp tile 64x64 (32 acc fragments),
// MMA:LDSM = 6:1 per kk-step for high tensor-pipe occupancy per warp.
// ---------------------------------------------------------------------------
template <int EPI>
__global__ __launch_bounds__(128, 2)
void gemm_kernel(const float* __restrict__ bias) {
    extern __shared__ __align__(16) __nv_bfloat16 smem[];

    const __nv_bfloat16* __restrict__ Wh   = (EPI == 1) ? g_W1h : g_W2h;
    const __nv_bfloat16* __restrict__ Wl   = (EPI == 1) ? g_W1l : g_W2l;
    const __nv_bfloat16* __restrict__ Ah_g = (EPI == 1) ? g_hh : g_th;
    const __nv_bfloat16* __restrict__ Al_g = (EPI == 1) ? g_hl : g_tl;

    const int tid  = threadIdx.x;
    const int lane = tid & 31;
    const int wid  = tid >> 5;
    const int wm   = wid >> 1;     // 0..1
    const int wn   = wid & 1;      // 0..1
    const int gid  = lane >> 2;
    const int t4   = lane & 3;
    const int bm0  = blockIdx.y * BM;
    const int bn0  = blockIdx.x * BN;

    // cp.async: thread owns row=tid of each array, all 4 chunks
    const __nv_bfloat16* gAh0 = Ah_g + (size_t)(bm0 + tid) * DIM;
    const __nv_bfloat16* gAl0 = Al_g + (size_t)(bm0 + tid) * DIM;
    const __nv_bfloat16* gWh0 = Wh   + (size_t)(bn0 + tid) * DIM;
    const __nv_bfloat16* gWl0 = Wl   + (size_t)(bn0 + tid) * DIM;

    const unsigned s_base = smem_u32(smem);
    unsigned offc[4];
#pragma unroll
    for (int c = 0; c < 4; ++c) offc[c] = swoff(tid, c);

    auto issue_stage = [&](int s) {
        const unsigned sb = s_base + (unsigned)((s % STAGES) * STAGE_BYTES);
        const int ko = s * BK;
#pragma unroll
        for (int c = 0; c < 4; ++c) {
            cp16(sb + offc[c],                 gAh0 + ko + c * 8);
            cp16(sb + ARR_BYTES + offc[c],     gAl0 + ko + c * 8);
            cp16(sb + 2 * ARR_BYTES + offc[c], gWh0 + ko + c * 8);
            cp16(sb + 3 * ARR_BYTES + offc[c], gWl0 + ko + c * 8);
        }
    };

    // ldmatrix lane address components
    const int rowA = wm * 64 + (lane & 15);                   // + mi*16
    const int chA  = lane >> 4;                               // + kk*2
    const int rowB = wn * 64 + (lane >> 4) * 8 + (lane & 7);  // + p*16
    const int chB  = (lane >> 3) & 1;                         // + kk*2

    float acc[4][8][4];
#pragma unroll
    for (int i = 0; i < 4; ++i)
#pragma unroll
        for (int j = 0; j < 8; ++j)
#pragma unroll
            for (int c = 0; c < 4; ++c) acc[i][j][c] = 0.f;

    const int NST = DIM / BK;  // 32

    issue_stage(0);
    cp_commit();
    issue_stage(1);
    cp_commit();

    for (int s = 0; s < NST; ++s) {
        cp_wait<1>();            // stage s resident
        __syncthreads();         // all copies visible; iter s-1 reads complete
        if (s + 2 < NST) issue_stage(s + 2);   // refill buffer read at iter s-1
        cp_commit();

        const unsigned ab = s_base + (unsigned)((s % STAGES) * STAGE_BYTES);
        const unsigned uAh = ab;
        const unsigned uAl = ab + ARR_BYTES;
        const unsigned uBh = ab + 2 * ARR_BYTES;
        const unsigned uBl = ab + 3 * ARR_BYTES;

#pragma unroll
        for (int kk = 0; kk < 2; ++kk) {
            unsigned afh[4][4], afl[4][4], bfh[8][2], bfl[8][2];
#pragma unroll
            for (int mi = 0; mi < 4; ++mi) {
                const unsigned off = swoff(rowA + mi * 16, kk * 2 + chA);
                LDSM_X4(afh[mi], uAh + off);
                LDSM_X4(afl[mi], uAl + off);
            }
#pragma unroll
            for (int p = 0; p < 4; ++p) {
                const unsigned off = swoff(rowB + p * 16, kk * 2 + chB);
                unsigned rh[4], rl[4];
                LDSM_X4(rh, uBh + off);
                LDSM_X4(rl, uBl + off);
                bfh[2 * p][0] = rh[0]; bfh[2 * p][1] = rh[1];
                bfh[2 * p + 1][0] = rh[2]; bfh[2 * p + 1][1] = rh[3];
                bfl[2 * p][0] = rl[0]; bfl[2 * p][1] = rl[1];
                bfl[2 * p + 1][0] = rl[2]; bfl[2 * p + 1][1] = rl[3];
            }
#pragma unroll
            for (int mi = 0; mi < 4; ++mi)
#pragma unroll
                for (int nj = 0; nj < 8; ++nj) {
                    mma16816(acc[mi][nj], afh[mi], bfh[nj]);
                    mma16816(acc[mi][nj], afh[mi], bfl[nj]);
                    mma16816(acc[mi][nj], afl[mi], bfh[nj]);
                }
        }
    }

    // ---- epilogue ----
#pragma unroll
    for (int mi = 0; mi < 4; ++mi) {
#pragma unroll
        for (int rr = 0; rr < 2; ++rr) {
            const int r = bm0 + wm * 64 + mi * 16 + gid + rr * 8;
            if (EPI == 1) {
                __nv_bfloat16* th = g_th + (size_t)r * DIM;
                __nv_bfloat16* tl = g_tl + (size_t)r * DIM;
#pragma unroll
                for (int nj = 0; nj < 8; ++nj) {
                    const int col = bn0 + wn * 64 + nj * 8 + t4 * 2;
                    const float v0 = tanhf(acc[mi][nj][rr * 2 + 0] + bias[col]);
                    const float v1 = tanhf(acc[mi][nj][rr * 2 + 1] + bias[col + 1]);
                    __nv_bfloat162 h2, l2;
                    split2(v0, h2.x, l2.x);
                    split2(v1, h2.y, l2.y);
                    *reinterpret_cast<__nv_bfloat162*>(th + col) = h2;
                    *reinterpret_cast<__nv_bfloat162*>(tl + col) = l2;
                }
            } else {
                const float ce = g_coef[(size_t)r * 3 + 0];
                const float cc = g_coef[(size_t)r * 3 + 1];
                const float cn = g_coef[(size_t)r * 3 + 2];
                float* hrow = g_h + (size_t)r * DIM;
#pragma unroll
                for (int nj = 0; nj < 8; ++nj) {
                    const int col = bn0 + wn * 64 + nj * 8 + t4 * 2;
                    const float2 hv = *reinterpret_cast<const float2*>(hrow + col);
                    const float2 evv = *reinterpret_cast<const float2*>(g_dirs + col);
                    const float2 cvv = *reinterpret_cast<const float2*>(g_dirs + DIM + col);
                    const float2 nvv = *reinterpret_cast<const float2*>(g_dirs + 2 * DIM + col);
                    const float2 bv  = *reinterpret_cast<const float2*>(bias + col);
                    float2 o;
                    o.x = hv.x + acc[mi][nj][rr * 2 + 0] + bv.x
                        - ce * (hv.x - evv.x) - cc * (hv.x - cvv.x) - cn * (hv.x - nvv.x);
                    o.y = hv.y + acc[mi][nj][rr * 2 + 1] + bv.y
                        - ce * (hv.y - evv.y) - cc * (hv.y - cvv.y) - cn * (hv.y - nvv.y);
                    *reinterpret_cast<float2*>(hrow + col) = o;
                }
            }
        }
    }
}

// ---------------------------------------------------------------------------
// Warp-per-row final norm clamp -> d_out.
// ---------------------------------------------------------------------------
__global__ void final_kernel(float* __restrict__ out) {
    const int row  = (blockIdx.x * 256 + threadIdx.x) >> 5;
    const int lane = threadIdx.x & 31;
    float4 hv[8];
    float s2 = 0.f;
#pragma unroll
    for (int j = 0; j < 8; ++j) {
        hv[j] = reinterpret_cast<const float4*>(g_h + (size_t)row * DIM)[lane + j * 32];
        s2 += dot4(hv[j], hv[j]);
    }
#pragma unroll
    for (int o = 16; o; o >>= 1) s2 += __shfl_xor_sync(0xffffffffu, s2, o);
    const float nrm = sqrtf(s2);
    const float sc = (nrm > 10.0f) ? (10.0f / (nrm + 1e-8f)) : 1.0f;
#pragma unroll
    for (int j = 0; j < 8; ++j) {
        float4 v = hv[j];
        v.x *= sc; v.y *= sc; v.z *= sc; v.w *= sc;
        reinterpret_cast<float4*>(out + (size_t)row * DIM)[lane + j * 32] = v;
    }
}

extern "C" void kernel_launch(void* const* d_in, const int* in_sizes, int n_in,
                              void* d_out, int out_size) {
    (void)in_sizes; (void)n_in; (void)out_size;
    const float* h0 = (const float*)d_in[0];
    const float* W1 = (const float*)d_in[1];
    const float* b1 = (const float*)d_in[2];
    const float* W2 = (const float*)d_in[3];
    const float* b2 = (const float*)d_in[4];
    const float* ae = (const float*)d_in[5];
    const float* ac = (const float*)d_in[6];
    const float* an = (const float*)d_in[7];
    float* out = (float*)d_out;

    static bool s_attr_done = false;
    if (!s_attr_done) {
        cudaFuncSetAttribute(gemm_kernel<1>, cudaFuncAttributeMaxDynamicSharedMemorySize, SMEM_TOTAL_BYTES);
        cudaFuncSetAttribute(gemm_kernel<2>, cudaFuncAttributeMaxDynamicSharedMemorySize, SMEM_TOTAL_BYTES);
        s_attr_done = true;
    }

    anchor_kernel<<<3, 256>>>(ae, ac, an);
    wsplit_kernel<<<DIM * DIM / 256, 256>>>(W1, W2);

    const dim3 ggrid(DIM / BN, BATCH / BM);   // (8, 128) = 1024 CTAs
    for (int l = 0; l < NLAYERS; ++l) {
        if (l == 0)
            prep_kernel<<<BATCH / 8, 256>>>(h0, /*use_ext=*/1, /*do_clamp=*/0);
        else
            prep_kernel<<<BATCH / 8, 256>>>(nullptr, /*use_ext=*/0, /*do_clamp=*/1);
        gemm_kernel<1><<<ggrid, 128, SMEM_TOTAL_BYTES>>>(b1);
        gemm_kernel<2><<<ggrid, 128, SMEM_TOTAL_BYTES>>>(b2);
    }
    final_kernel<<<BATCH / 8, 256>>>(out);
}

// round 13
// speedup vs baseline: 1.5019x; 1.5019x over previous
#include <cuda_runtime.h>
#include <cuda_bf16.h>
#include <math.h>

#define BATCH 16384
#define DIM   1024
#define NLAYERS 6

#define BM 128
#define BN 128
#define BK 32
#define ASTR 40            // smem row stride (bf16): 32 + 8 pad
#define STAGES 2
#define TILE_ELEMS (BM * ASTR)
#define TILE_BYTES (TILE_ELEMS * 2)
#define STAGE_BYTES (4 * TILE_BYTES)
#define SMEM_TOTAL_BYTES (STAGES * STAGE_BYTES)  // 81920 B -> 2 CTAs/SM

// ---- scratch (allocation-free: __device__ globals; device-code refs only) ----
__device__ float g_h[(size_t)BATCH * DIM];
__device__ __nv_bfloat16 g_hh[(size_t)BATCH * DIM];
__device__ __nv_bfloat16 g_hl[(size_t)BATCH * DIM];
__device__ __nv_bfloat16 g_th[(size_t)BATCH * DIM];
__device__ __nv_bfloat16 g_tl[(size_t)BATCH * DIM];
__device__ __nv_bfloat16 g_W1h[DIM * DIM], g_W1l[DIM * DIM];
__device__ __nv_bfloat16 g_W2h[DIM * DIM], g_W2l[DIM * DIM];
__device__ float g_dirs[3 * DIM];
__device__ float g_dn2[3];
__device__ float g_coef[(size_t)BATCH * 3];
__device__ float g_scale[(size_t)BATCH];
__device__ float g_pstats[(size_t)BATCH * 32 * 4];   // per (row, nCTA*4+wn): s2,de,dc,dn

static __device__ __forceinline__ float dot4(const float4 a, const float4 b) {
    return a.x * b.x + a.y * b.y + a.z * b.z + a.w * b.w;
}

static __device__ __forceinline__ void split2(float x, __nv_bfloat16& h, __nv_bfloat16& l) {
    h = __float2bfloat16(x);
    l = __float2bfloat16(x - __bfloat162float(h));
}

static __device__ __forceinline__ void mma16816(float* c, const unsigned* a, const unsigned* b) {
    asm volatile(
        "mma.sync.aligned.m16n8k16.row.col.f32.bf16.bf16.f32 "
        "{%0,%1,%2,%3}, {%4,%5,%6,%7}, {%8,%9}, {%0,%1,%2,%3};\n"
        : "+f"(c[0]), "+f"(c[1]), "+f"(c[2]), "+f"(c[3])
        : "r"(a[0]), "r"(a[1]), "r"(a[2]), "r"(a[3]), "r"(b[0]), "r"(b[1]));
}

#define LDSM_X4(r, a) \
    asm volatile("ldmatrix.sync.aligned.m8n8.x4.shared.b16 {%0,%1,%2,%3}, [%4];" \
        : "=r"((r)[0]), "=r"((r)[1]), "=r"((r)[2]), "=r"((r)[3]) : "r"(a))

static __device__ __forceinline__ unsigned smem_u32(const void* p) {
    return (unsigned)__cvta_generic_to_shared(p);
}

static __device__ __forceinline__ void cp16(unsigned dst, const void* src) {
    asm volatile("cp.async.cg.shared.global [%0], [%1], 16;\n" :: "r"(dst), "l"(src));
}
static __device__ __forceinline__ void cp_commit() {
    asm volatile("cp.async.commit_group;\n");
}
template <int N>
static __device__ __forceinline__ void cp_wait() {
    asm volatile("cp.async.wait_group %0;\n" :: "n"(N));
}

// ---------------------------------------------------------------------------
__global__ void wsplit_kernel(const float* __restrict__ W1, const float* __restrict__ W2) {
    const size_t i = (size_t)blockIdx.x * 256 + threadIdx.x;
    float x = W1[i];
    split2(x, g_W1h[i], g_W1l[i]);
    x = W2[i];
    split2(x, g_W2h[i], g_W2l[i]);
}

__global__ void anchor_kernel(const float* __restrict__ ae,
                              const float* __restrict__ ac,
                              const float* __restrict__ an) {
    const int b = blockIdx.x;
    const int t = threadIdx.x;
    const float* src = (b == 0) ? ae : ((b == 1) ? ac : an);
    float4 v = reinterpret_cast<const float4*>(src)[t];
    float s = dot4(v, v);
#pragma unroll
    for (int o = 16; o; o >>= 1) s += __shfl_down_sync(0xffffffffu, s, o);
    __shared__ float sh[8];
    if ((t & 31) == 0) sh[t >> 5] = s;
    __syncthreads();
    __shared__ float s_inv;
    if (t == 0) {
        float tot = 0.f;
#pragma unroll
        for (int i = 0; i < 8; ++i) tot += sh[i];
        s_inv = 1.0f / fmaxf(sqrtf(tot), 1e-12f);
    }
    __syncthreads();
    const float inv = s_inv;
    v.x *= inv; v.y *= inv; v.z *= inv; v.w *= inv;
    reinterpret_cast<float4*>(g_dirs + (size_t)b * DIM)[t] = v;

    float s2 = dot4(v, v);
#pragma unroll
    for (int o = 16; o; o >>= 1) s2 += __shfl_down_sync(0xffffffffu, s2, o);
    __syncthreads();
    if ((t & 31) == 0) sh[t >> 5] = s2;
    __syncthreads();
    if (t == 0) {
        float tot = 0.f;
#pragma unroll
        for (int i = 0; i < 8; ++i) tot += sh[i];
        g_dn2[b] = tot;
    }
}

// ---------------------------------------------------------------------------
// Layer-0 prep: stats + coefs from h0 (no clamp), write h/split, scale=1.
// Warp-per-row, 8 rows per 256-block.
// ---------------------------------------------------------------------------
__global__ void prep0_kernel(const float* __restrict__ Hext) {
    const int row  = (blockIdx.x * 256 + threadIdx.x) >> 5;
    const int lane = threadIdx.x & 31;
    const float* hrow = Hext + (size_t)row * DIM;

    float4 hv[8];
    float s2 = 0.f, de = 0.f, dc = 0.f, dn = 0.f;
#pragma unroll
    for (int j = 0; j < 8; ++j) {
        const int idx = lane + j * 32;
        hv[j] = reinterpret_cast<const float4*>(hrow)[idx];
        const float4 ev = reinterpret_cast<const float4*>(g_dirs)[idx];
        const float4 cv = reinterpret_cast<const float4*>(g_dirs + DIM)[idx];
        const float4 nv = reinterpret_cast<const float4*>(g_dirs + 2 * DIM)[idx];
        s2 += dot4(hv[j], hv[j]);
        de += dot4(hv[j], ev);
        dc += dot4(hv[j], cv);
        dn += dot4(hv[j], nv);
    }
#pragma unroll
    for (int o = 16; o; o >>= 1) {
        s2 += __shfl_xor_sync(0xffffffffu, s2, o);
        de += __shfl_xor_sync(0xffffffffu, de, o);
        dc += __shfl_xor_sync(0xffffffffu, dc, o);
        dn += __shfl_xor_sync(0xffffffffu, dn, o);
    }

    if (lane == 0) {
        const float hn = fmaxf(sqrtf(s2), 1e-12f);
        const float a_e = de / hn, a_c = dc / hn, a_n = dn / hn;
        const float div_e = 1.0f - a_e, div_c = 1.0f - a_c, div_n = 1.0f - a_n;
        const float boundary = fminf(fmaxf(1.0f - fabsf(a_e - a_c), 0.0f), 1.0f);
        const float fe = fmaxf(sqrtf(fmaxf(s2 - 2.0f * de + g_dn2[0], 0.0f)), 1e-12f);
        const float fc = fmaxf(sqrtf(fmaxf(s2 - 2.0f * dc + g_dn2[1], 0.0f)), 1e-12f);
        const float fn = fmaxf(sqrtf(fmaxf(s2 - 2.0f * dn + g_dn2[2], 0.0f)), 1e-12f);
        g_coef[(size_t)row * 3 + 0] = 0.1f  * div_e / fe;
        g_coef[(size_t)row * 3 + 1] = 0.1f  * div_c / fc;
        g_coef[(size_t)row * 3 + 2] = (0.05f * div_n + 0.05f * boundary) / fn;
        g_scale[row] = 1.0f;
    }

#pragma unroll
    for (int j = 0; j < 8; ++j) {
        const int idx = lane + j * 32;
        const float4 v = hv[j];
        reinterpret_cast<float4*>(g_h + (size_t)row * DIM)[idx] = v;
        __nv_bfloat16 hh[4], hl[4];
        split2(v.x, hh[0], hl[0]);
        split2(v.y, hh[1], hl[1]);
        split2(v.z, hh[2], hl[2]);
        split2(v.w, hh[3], hl[3]);
        reinterpret_cast<uint2*>(g_hh + (size_t)row * DIM)[idx] = *reinterpret_cast<uint2*>(hh);
        reinterpret_cast<uint2*>(g_hl + (size_t)row * DIM)[idx] = *reinterpret_cast<uint2*>(hl);
    }
}

// ---------------------------------------------------------------------------
// preplite: one thread per row. Sum 32 partial stats, fold clamp into scale,
// compute coefs. Deterministic (fixed summation order).
// ---------------------------------------------------------------------------
__global__ void preplite_kernel() {
    const int row = blockIdx.x * 256 + threadIdx.x;
    const float4* p = reinterpret_cast<const float4*>(g_pstats + (size_t)row * 128);
    float s2 = 0.f, de = 0.f, dc = 0.f, dn = 0.f;
#pragma unroll
    for (int i = 0; i < 32; ++i) {
        const float4 v = p[i];
        s2 += v.x; de += v.y; dc += v.z; dn += v.w;
    }
    const float nrm = sqrtf(s2);
    const float scale = (nrm > 10.0f) ? (10.0f / (nrm + 1e-8f)) : 1.0f;
    const float S2 = s2 * scale * scale;
    const float DE = de * scale, DC = dc * scale, DN = dn * scale;

    const float hn = fmaxf(sqrtf(S2), 1e-12f);
    const float a_e = DE / hn, a_c = DC / hn, a_n = DN / hn;
    const float div_e = 1.0f - a_e, div_c = 1.0f - a_c, div_n = 1.0f - a_n;
    const float boundary = fminf(fmaxf(1.0f - fabsf(a_e - a_c), 0.0f), 1.0f);
    const float fe = fmaxf(sqrtf(fmaxf(S2 - 2.0f * DE + g_dn2[0], 0.0f)), 1e-12f);
    const float fc = fmaxf(sqrtf(fmaxf(S2 - 2.0f * DC + g_dn2[1], 0.0f)), 1e-12f);
    const float fn = fmaxf(sqrtf(fmaxf(S2 - 2.0f * DN + g_dn2[2], 0.0f)), 1e-12f);
    g_coef[(size_t)row * 3 + 0] = 0.1f  * div_e / fe;
    g_coef[(size_t)row * 3 + 1] = 0.1f  * div_c / fc;
    g_coef[(size_t)row * 3 + 2] = (0.05f * div_n + 0.05f * boundary) / fn;
    g_scale[row] = scale;
}

// ---------------------------------------------------------------------------
// Tensor-core NT GEMM (R8-proven config): bf16x3, 128x128x32, padded smem,
// 2-stage cp.async, 2 CTAs/SM, ldmatrix loads. 8 warps (2x4), warp tile 64x32.
// EPI=1: tanh(scale*acc + b) -> split to g_th/g_tl.
// EPI=2: deferred-clamp collapse update; writes unclamped h + split + partial stats.
// ---------------------------------------------------------------------------
template <int EPI>
__global__ __launch_bounds__(256, 2)
void gemm_kernel(const float* __restrict__ bias) {
    extern __shared__ __align__(16) __nv_bfloat16 smem[];

    const __nv_bfloat16* __restrict__ Wh   = (EPI == 1) ? g_W1h : g_W2h;
    const __nv_bfloat16* __restrict__ Wl   = (EPI == 1) ? g_W1l : g_W2l;
    const __nv_bfloat16* __restrict__ Ah_g = (EPI == 1) ? g_hh : g_th;
    const __nv_bfloat16* __restrict__ Al_g = (EPI == 1) ? g_hl : g_tl;

    const int tid  = threadIdx.x;
    const int lane = tid & 31;
    const int wid  = tid >> 5;
    const int wm   = wid >> 2;
    const int wn   = wid & 3;
    const int gid  = lane >> 2;
    const int t4   = lane & 3;
    const int bm0  = blockIdx.y * BM;
    const int bn0  = blockIdx.x * BN;

    const int cr0 = tid >> 2;
    const int cc0 = (tid & 3) * 8;

    const __nv_bfloat16* gAh0 = Ah_g + (size_t)(bm0 + cr0) * DIM + cc0;
    const __nv_bfloat16* gAl0 = Al_g + (size_t)(bm0 + cr0) * DIM + cc0;
    const __nv_bfloat16* gWh0 = Wh   + (size_t)(bn0 + cr0) * DIM + cc0;
    const __nv_bfloat16* gWl0 = Wl   + (size_t)(bn0 + cr0) * DIM + cc0;
    const size_t rstep = (size_t)64 * DIM;

    const unsigned s_base = smem_u32(smem);
    const unsigned s_off0 = (unsigned)(cr0 * ASTR + cc0) * 2u;
    const unsigned s_off1 = s_off0 + (unsigned)(64 * ASTR) * 2u;

    auto issue_stage = [&](int s) {
        const unsigned sb = s_base + (unsigned)((s % STAGES) * STAGE_BYTES);
        const int ko = s * BK;
        cp16(sb + s_off0,                  gAh0 + ko);
        cp16(sb + s_off1,                  gAh0 + rstep + ko);
        cp16(sb + TILE_BYTES + s_off0,     gAl0 + ko);
        cp16(sb + TILE_BYTES + s_off1,     gAl0 + rstep + ko);
        cp16(sb + 2 * TILE_BYTES + s_off0, gWh0 + ko);
        cp16(sb + 2 * TILE_BYTES + s_off1, gWh0 + rstep + ko);
        cp16(sb + 3 * TILE_BYTES + s_off0, gWl0 + ko);
        cp16(sb + 3 * TILE_BYTES + s_off1, gWl0 + rstep + ko);
    };

    const int rA = wm * 64 + (lane & 15);
    const int cA = (lane >> 4) * 8;
    const int rB = wn * 32 + (lane >> 4) * 8 + (lane & 7);
    const int cB = ((lane >> 3) & 1) * 8;

    float acc[4][4][4];
#pragma unroll
    for (int i = 0; i < 4; ++i)
#pragma unroll
        for (int j = 0; j < 4; ++j)
#pragma unroll
            for (int c = 0; c < 4; ++c) acc[i][j][c] = 0.f;

    const int NST = DIM / BK;  // 32

    issue_stage(0);
    cp_commit();

    for (int s = 0; s < NST; ++s) {
        if (s + STAGES - 1 < NST) issue_stage(s + STAGES - 1);
        cp_commit();
        cp_wait<STAGES - 1>();
        __syncthreads();

        const unsigned ab = s_base + (unsigned)((s % STAGES) * STAGE_BYTES);
        const unsigned uAh = ab;
        const unsigned uAl = ab + TILE_BYTES;
        const unsigned uBh = ab + 2 * TILE_BYTES;
        const unsigned uBl = ab + 3 * TILE_BYTES;

#pragma unroll
        for (int kk = 0; kk < 2; ++kk) {
            unsigned afh[4][4], afl[4][4], bfh[4][2], bfl[4][2];
#pragma unroll
            for (int mi = 0; mi < 4; ++mi) {
                const unsigned off = (unsigned)(((rA + mi * 16) * ASTR) + kk * 16 + cA) * 2u;
                LDSM_X4(afh[mi], uAh + off);
                LDSM_X4(afl[mi], uAl + off);
            }
#pragma unroll
            for (int p = 0; p < 2; ++p) {
                const unsigned off = (unsigned)(((rB + p * 16) * ASTR) + kk * 16 + cB) * 2u;
                unsigned rh[4], rl[4];
                LDSM_X4(rh, uBh + off);
                LDSM_X4(rl, uBl + off);
                bfh[2 * p][0] = rh[0]; bfh[2 * p][1] = rh[1];
                bfh[2 * p + 1][0] = rh[2]; bfh[2 * p + 1][1] = rh[3];
                bfl[2 * p][0] = rl[0]; bfl[2 * p][1] = rl[1];
                bfl[2 * p + 1][0] = rl[2]; bfl[2 * p + 1][1] = rl[3];
            }
#pragma unroll
            for (int mi = 0; mi < 4; ++mi)
#pragma unroll
                for (int nj = 0; nj < 4; ++nj) {
                    mma16816(acc[mi][nj], afh[mi], bfh[nj]);
                    mma16816(acc[mi][nj], afh[mi], bfl[nj]);
                    mma16816(acc[mi][nj], afl[mi], bfh[nj]);
                }
        }
        if (s + 1 < NST) __syncthreads();
    }

    // ---- epilogue ----
#pragma unroll
    for (int mi = 0; mi < 4; ++mi) {
#pragma unroll
        for (int rr = 0; rr < 2; ++rr) {
            const int r = bm0 + wm * 64 + mi * 16 + gid + rr * 8;
            const float sc = g_scale[r];
            if (EPI == 1) {
                __nv_bfloat16* th = g_th + (size_t)r * DIM;
                __nv_bfloat16* tl = g_tl + (size_t)r * DIM;
#pragma unroll
                for (int nj = 0; nj < 4; ++nj) {
                    const int col = bn0 + wn * 32 + nj * 8 + t4 * 2;
                    const float v0 = tanhf(sc * acc[mi][nj][rr * 2 + 0] + bias[col]);
                    const float v1 = tanhf(sc * acc[mi][nj][rr * 2 + 1] + bias[col + 1]);
                    __nv_bfloat162 h2, l2;
                    split2(v0, h2.x, l2.x);
                    split2(v1, h2.y, l2.y);
                    *reinterpret_cast<__nv_bfloat162*>(th + col) = h2;
                    *reinterpret_cast<__nv_bfloat162*>(tl + col) = l2;
                }
            } else {
                const float ce = g_coef[(size_t)r * 3 + 0];
                const float cc = g_coef[(size_t)r * 3 + 1];
                const float cn = g_coef[(size_t)r * 3 + 2];
                float* hrow = g_h + (size_t)r * DIM;
                __nv_bfloat16* hh = g_hh + (size_t)r * DIM;
                __nv_bfloat16* hl = g_hl + (size_t)r * DIM;
                float p2 = 0.f, pe = 0.f, pc = 0.f, pn = 0.f;
#pragma unroll
                for (int nj = 0; nj < 4; ++nj) {
                    const int col = bn0 + wn * 32 + nj * 8 + t4 * 2;
                    const float2 hv = *reinterpret_cast<const float2*>(hrow + col);
                    const float2 evv = *reinterpret_cast<const float2*>(g_dirs + col);
                    const float2 cvv = *reinterpret_cast<const float2*>(g_dirs + DIM + col);
                    const float2 nvv = *reinterpret_cast<const float2*>(g_dirs + 2 * DIM + col);
                    const float2 bv  = *reinterpret_cast<const float2*>(bias + col);
                    const float hx = sc * hv.x, hy = sc * hv.y;
                    float2 o;
                    o.x = hx + acc[mi][nj][rr * 2 + 0] + bv.x
                        - ce * (hx - evv.x) - cc * (hx - cvv.x) - cn * (hx - nvv.x);
                    o.y = hy + acc[mi][nj][rr * 2 + 1] + bv.y
                        - ce * (hy - evv.y) - cc * (hy - cvv.y) - cn * (hy - nvv.y);
                    *reinterpret_cast<float2*>(hrow + col) = o;
                    __nv_bfloat162 h2, l2;
                    split2(o.x, h2.x, l2.x);
                    split2(o.y, h2.y, l2.y);
                    *reinterpret_cast<__nv_bfloat162*>(hh + col) = h2;
                    *reinterpret_cast<__nv_bfloat162*>(hl + col) = l2;
                    p2 += o.x * o.x + o.y * o.y;
                    pe += o.x * evv.x + o.y * evv.y;
                    pc += o.x * cvv.x + o.y * cvv.y;
                    pn += o.x * nvv.x + o.y * nvv.y;
                }
                // reduce across the 4 lanes (t4) that share row r
#pragma unroll
                for (int o = 1; o < 4; o <<= 1) {
                    p2 += __shfl_xor_sync(0xffffffffu, p2, o);
                    pe += __shfl_xor_sync(0xffffffffu, pe, o);
                    pc += __shfl_xor_sync(0xffffffffu, pc, o);
                    pn += __shfl_xor_sync(0xffffffffu, pn, o);
                }
                if (t4 == 0) {
                    float4* dst = reinterpret_cast<float4*>(
                        g_pstats + ((size_t)r * 32 + (size_t)blockIdx.x * 4 + wn) * 4);
                    *dst = make_float4(p2, pe, pc, pn);
                }
            }
        }
    }
}

// ---------------------------------------------------------------------------
// Warp-per-row final norm clamp -> d_out (applies the last deferred clamp).
// ---------------------------------------------------------------------------
__global__ void final_kernel(float* __restrict__ out) {
    const int row  = (blockIdx.x * 256 + threadIdx.x) >> 5;
    const int lane = threadIdx.x & 31;
    float4 hv[8];
    float s2 = 0.f;
#pragma unroll
    for (int j = 0; j < 8; ++j) {
        hv[j] = reinterpret_cast<const float4*>(g_h + (size_t)row * DIM)[lane + j * 32];
        s2 += dot4(hv[j], hv[j]);
    }
#pragma unroll
    for (int o = 16; o; o >>= 1) s2 += __shfl_xor_sync(0xffffffffu, s2, o);
    const float nrm = sqrtf(s2);
    const float sc = (nrm > 10.0f) ? (10.0f / (nrm + 1e-8f)) : 1.0f;
#pragma unroll
    for (int j = 0; j < 8; ++j) {
        float4 v = hv[j];
        v.x *= sc; v.y *= sc; v.z *= sc; v.w *= sc;
        reinterpret_cast<float4*>(out + (size_t)row * DIM)[lane + j * 32] = v;
    }
}

extern "C" void kernel_launch(void* const* d_in, const int* in_sizes, int n_in,
                              void* d_out, int out_size) {
    (void)in_sizes; (void)n_in; (void)out_size;
    const float* h0 = (const float*)d_in[0];
    const float* W1 = (const float*)d_in[1];
    const float* b1 = (const float*)d_in[2];
    const float* W2 = (const float*)d_in[3];
    const float* b2 = (const float*)d_in[4];
    const float* ae = (const float*)d_in[5];
    const float* ac = (const float*)d_in[6];
    const float* an = (const float*)d_in[7];
    float* out = (float*)d_out;

    static bool s_attr_done = false;
    if (!s_attr_done) {
        cudaFuncSetAttribute(gemm_kernel<1>, cudaFuncAttributeMaxDynamicSharedMemorySize, SMEM_TOTAL_BYTES);
        cudaFuncSetAttribute(gemm_kernel<2>, cudaFuncAttributeMaxDynamicSharedMemorySize, SMEM_TOTAL_BYTES);
        s_attr_done = true;
    }

    anchor_kernel<<<3, 256>>>(ae, ac, an);
    wsplit_kernel<<<DIM * DIM / 256, 256>>>(W1, W2);
    prep0_kernel<<<BATCH / 8, 256>>>(h0);

    const dim3 ggrid(DIM / BN, BATCH / BM);   // (8, 128)
    for (int l = 0; l < NLAYERS; ++l) {
        if (l > 0) preplite_kernel<<<BATCH / 256, 256>>>();
        gemm_kernel<1><<<ggrid, 256, SMEM_TOTAL_BYTES>>>(b1);
        gemm_kernel<2><<<ggrid, 256, SMEM_TOTAL_BYTES>>>(b2);
    }
    final_kernel<<<BATCH / 8, 256>>>(out);
}